// round 17
// baseline (speedup 1.0000x reference)
#include <cuda_runtime.h>
#include <cuda_fp16.h>
#include <cstdint>
#include <cstddef>

#define MM 8192
#define KK 4096
#define OO 4096

#define BM 128
#define BN 256
#define BK 128                   // int8 k-elems per stage = 128 bytes/row
#define KITERS 64                // 2 planes x (4096/128)
#define STAGES 3
#define ROWB 144                 // bytes per smem row (128 data + 16 pad): conflict-free
#define A_STAGE_BYTES (BM * ROWB)                 // 18432
#define B_STAGE_BYTES (BN * ROWB)                 // 36864
#define STAGE_BYTES   (A_STAGE_BYTES + B_STAGE_BYTES)  // 55296
#define SMEM_BYTES    (STAGES * STAGE_BYTES)      // 165888

// Scratch (device globals only -- no allocation allowed)
__device__ int8_t g_W1[(size_t)OO * KK];   // 16 MB: 127*w  (0, +127, -127)
__device__ int8_t g_W2[(size_t)OO * KK];   // 16 MB: w      (0, +1, -1)
__device__ int8_t g_Aq[2ull * MM * KK];    // 64 MB: [q1 plane | q2 plane]
__device__ float  g_sf[MM];                // s/127 per row = rowmax/(127*127)

// ---------------- PTX helpers ----------------
__device__ __forceinline__ uint32_t smem_u32(const void* p) {
    uint32_t a;
    asm("{ .reg .u64 t; cvta.to.shared.u64 t, %1; cvt.u32.u64 %0, t; }" : "=r"(a) : "l"(p));
    return a;
}
#define CP16(dst, src) \
    asm volatile("cp.async.cg.shared.global [%0], [%1], 16;" :: "r"(dst), "l"(src) : "memory")
#define CP_COMMIT() asm volatile("cp.async.commit_group;" ::: "memory")
#define CP_WAIT(n)  asm volatile("cp.async.wait_group %0;" :: "n"(n) : "memory")

__device__ __forceinline__ void ldsm_x4(uint32_t& r0, uint32_t& r1, uint32_t& r2, uint32_t& r3,
                                        uint32_t addr) {
    asm volatile("ldmatrix.sync.aligned.m8n8.x4.shared.b16 {%0,%1,%2,%3}, [%4];"
                 : "=r"(r0), "=r"(r1), "=r"(r2), "=r"(r3) : "r"(addr));
}
__device__ __forceinline__ void imma16832(int* c, const uint32_t* a, const uint32_t* b) {
    asm volatile(
        "mma.sync.aligned.m16n8k32.row.col.s32.s8.s8.s32 "
        "{%0,%1,%2,%3}, {%4,%5,%6,%7}, {%8,%9}, {%0,%1,%2,%3};"
        : "+r"(c[0]), "+r"(c[1]), "+r"(c[2]), "+r"(c[3])
        : "r"(a[0]), "r"(a[1]), "r"(a[2]), "r"(a[3]), "r"(b[0]), "r"(b[1]));
}

// ---------------- Kernel 1: unpack ternary -> two int8 weight planes ----------------
__global__ void unpack_w_kernel(const int* __restrict__ nz, const int* __restrict__ sgn) {
    int idx = blockIdx.x * 256 + threadIdx.x;      // word index, OO*KK/32 total
    uint32_t nzv = (uint32_t)nz[idx];
    uint32_t sgv = (uint32_t)sgn[idx];
    uint32_t p1[8], p2[8];
#pragma unroll
    for (int w = 0; w < 8; w++) {
        uint32_t v1 = 0, v2 = 0;
#pragma unroll
        for (int b = 0; b < 4; b++) {
            int bit = w * 4 + b;
            uint32_t on = (nzv >> bit) & 1u;
            uint32_t sg = (sgv >> bit) & 1u;
            // w1 = on ? (sg ? -127 : 127) : 0 ; w2 = on ? (sg ? -1 : 1) : 0
            uint32_t b1 = on ? (sg ? 0x81u : 0x7Fu) : 0u;
            uint32_t b2 = on ? (sg ? 0xFFu : 0x01u) : 0u;
            v1 |= b1 << (8 * b);
            v2 |= b2 << (8 * b);
        }
        p1[w] = v1; p2[w] = v2;
    }
    uint4* d1 = reinterpret_cast<uint4*>(g_W1 + (size_t)idx * 32);
    uint4* d2 = reinterpret_cast<uint4*>(g_W2 + (size_t)idx * 32);
    d1[0] = make_uint4(p1[0], p1[1], p1[2], p1[3]);
    d1[1] = make_uint4(p1[4], p1[5], p1[6], p1[7]);
    d2[0] = make_uint4(p2[0], p2[1], p2[2], p2[3]);
    d2[1] = make_uint4(p2[4], p2[5], p2[6], p2[7]);
}

// ---------------- Kernel 2: per-row quantize x -> q1,q2 int8 planes + scale ----------------
__global__ void quantize_x_kernel(const float4* __restrict__ x) {
    int row = blockIdx.x;
    int t = threadIdx.x;           // 256
    const float4* xr = x + (size_t)row * (KK / 4);
    float4 v[4];
    float mx = 0.f;
#pragma unroll
    for (int j = 0; j < 4; j++) {
        v[j] = xr[j * 256 + t];
        mx = fmaxf(mx, fmaxf(fmaxf(fabsf(v[j].x), fabsf(v[j].y)),
                             fmaxf(fabsf(v[j].z), fabsf(v[j].w))));
    }
    __shared__ float red[256];
    red[t] = mx;
    __syncthreads();
#pragma unroll
    for (int s = 128; s > 0; s >>= 1) {
        if (t < s) red[t] = fmaxf(red[t], red[t + s]);
        __syncthreads();
    }
    float rmax = fmaxf(red[0], 1e-20f);
    float s    = rmax * (1.f / 127.f);
    float invs = 127.f / rmax;
    if (t == 0) g_sf[row] = rmax * (1.f / (127.f * 127.f));   // s/127

    uint32_t* q1 = reinterpret_cast<uint32_t*>(g_Aq) + (size_t)row * (KK / 4);
    uint32_t* q2 = reinterpret_cast<uint32_t*>(g_Aq + (size_t)MM * KK) + (size_t)row * (KK / 4);
#pragma unroll
    for (int j = 0; j < 4; j++) {
        int a0 = __float2int_rn(v[j].x * invs);
        int a1 = __float2int_rn(v[j].y * invs);
        int a2 = __float2int_rn(v[j].z * invs);
        int a3 = __float2int_rn(v[j].w * invs);
        int b0 = __float2int_rn((v[j].x - s * (float)a0) * invs * 127.f);
        int b1 = __float2int_rn((v[j].y - s * (float)a1) * invs * 127.f);
        int b2 = __float2int_rn((v[j].z - s * (float)a2) * invs * 127.f);
        int b3 = __float2int_rn((v[j].w - s * (float)a3) * invs * 127.f);
        uint32_t w1 = (a0 & 0xFF) | ((a1 & 0xFF) << 8) | ((a2 & 0xFF) << 16) | ((uint32_t)(a3 & 0xFF) << 24);
        uint32_t w2 = (b0 & 0xFF) | ((b1 & 0xFF) << 8) | ((b2 & 0xFF) << 16) | ((uint32_t)(b3 & 0xFF) << 24);
        q1[j * 256 + t] = w1;
        q2[j * 256 + t] = w2;
    }
}

// ---------------- Kernel 3: pipelined IMMA GEMM (single s32 accumulator) ----------------
__global__ void __launch_bounds__(256, 1)
gemm_kernel(const float* __restrict__ alpha, const float* __restrict__ bias,
            float* __restrict__ out) {
    extern __shared__ __align__(16) char smem[];
    uint32_t sb = smem_u32(smem);
    int tid = threadIdx.x, lane = tid & 31, wid = tid >> 5;
    int wm = wid & 1;              // 2 warps along M
    int wn = wid >> 1;             // 4 warps along N
    int cid = blockIdx.x;
    int nt = cid & 15;             // 16 N-tiles of 256
    int mt = cid >> 4;             // 64 M-tiles of 128

    // loader mapping: lr = tid>>3 (0..31), lc = tid&7 (16B chunk of 128B row)
    int lr = tid >> 3, lc = tid & 7;
    int arow = mt * BM + lr;
    int brow = nt * BN + lr;
    uint32_t sA = sb + (uint32_t)(lr * ROWB + lc * 16);
    uint32_t sB = sb + A_STAGE_BYTES + (uint32_t)(lr * ROWB + lc * 16);

    // kk in [0,64): plane = kk>>5 (0:q1/W1, 1:q2/W2), koff = (kk&31)*128 bytes
#define LOAD_STAGE(st, kk) do { \
    uint32_t _so = (uint32_t)(st) * STAGE_BYTES; \
    const int8_t* _ga = g_Aq + ((size_t)((kk) >> 5) * MM) * KK + (size_t)arow * KK + ((kk) & 31) * 128 + lc * 16; \
    const int8_t* _gb = (((kk) < 32) ? g_W1 : g_W2) + (size_t)brow * KK + ((kk) & 31) * 128 + lc * 16; \
    CP16(sA + _so,              _ga); \
    CP16(sA + _so + 32*ROWB,    _ga + (size_t)32*KK); \
    CP16(sA + _so + 64*ROWB,    _ga + (size_t)64*KK); \
    CP16(sA + _so + 96*ROWB,    _ga + (size_t)96*KK); \
    CP16(sB + _so,              _gb); \
    CP16(sB + _so + 32*ROWB,    _gb + (size_t)32*KK); \
    CP16(sB + _so + 64*ROWB,    _gb + (size_t)64*KK); \
    CP16(sB + _so + 96*ROWB,    _gb + (size_t)96*KK); \
    CP16(sB + _so + 128*ROWB,   _gb + (size_t)128*KK); \
    CP16(sB + _so + 160*ROWB,   _gb + (size_t)160*KK); \
    CP16(sB + _so + 192*ROWB,   _gb + (size_t)192*KK); \
    CP16(sB + _so + 224*ROWB,   _gb + (size_t)224*KK); \
} while (0)

    // prologue: stages 0,1
    LOAD_STAGE(0, 0); CP_COMMIT();
    LOAD_STAGE(1, 1); CP_COMMIT();

    int acc[4][8][4];
#pragma unroll
    for (int i = 0; i < 4; i++)
#pragma unroll
        for (int j = 0; j < 8; j++)
#pragma unroll
            for (int k = 0; k < 4; k++) acc[i][j][k] = 0;

    // per-lane ldmatrix base offsets (bytes); same tile geometry as fp16 version
    uint32_t aoff = (uint32_t)((wm * 64 + (lane & 15)) * ROWB + (lane >> 4) * 16);
    int bg = lane >> 3;  // 0..3
    uint32_t boff = (uint32_t)((wn * 64 + (bg & 1) * 8 + (lane & 7)) * ROWB + (bg >> 1) * 16);

    int st = 0;
    for (int kk = 0; kk < KITERS; kk++) {
        CP_WAIT(1);
        __syncthreads();
        if (kk + 2 < KITERS) {
            int wst = st + 2; if (wst >= STAGES) wst -= STAGES;
            LOAD_STAGE(wst, kk + 2);
        }
        CP_COMMIT();

        uint32_t stA = sb + (uint32_t)st * STAGE_BYTES;
        uint32_t stB = stA + A_STAGE_BYTES;
#pragma unroll
        for (int ks = 0; ks < 4; ks++) {            // 4 x k32 = 128 k-elems
            uint32_t a[4][4], b[8][2];
#pragma unroll
            for (int mi = 0; mi < 4; mi++)
                ldsm_x4(a[mi][0], a[mi][1], a[mi][2], a[mi][3],
                        stA + aoff + mi * (16 * ROWB) + ks * 32);
#pragma unroll
            for (int nj = 0; nj < 4; nj++) {
                uint32_t r0, r1, r2, r3;
                // B is col-major (k-contiguous per n) == W's [O][K] layout
                ldsm_x4(r0, r1, r2, r3, stB + boff + nj * (16 * ROWB) + ks * 32);
                b[2*nj][0] = r0; b[2*nj][1] = r2;
                b[2*nj+1][0] = r1; b[2*nj+1][1] = r3;
            }
#pragma unroll
            for (int mi = 0; mi < 4; mi++)
#pragma unroll
                for (int ni = 0; ni < 8; ni++)
                    imma16832(acc[mi][ni], a[mi], b[ni]);
        }
        if (++st == STAGES) st = 0;
    }

    // epilogue: y = D * (s_row/127) * alpha_col + bias_col
    int colbase = nt * BN + wn * 64;
    int rowbase = mt * BM + wm * 64;
#pragma unroll
    for (int mi = 0; mi < 4; mi++) {
        int r0 = rowbase + mi * 16 + (lane >> 2);
        float sf0 = __ldg(g_sf + r0);
        float sf1 = __ldg(g_sf + r0 + 8);
#pragma unroll
        for (int ni = 0; ni < 8; ni++) {
            int col = colbase + ni * 8 + (lane & 3) * 2;
            float2 av = *reinterpret_cast<const float2*>(alpha + col);
            float2 bv = *reinterpret_cast<const float2*>(bias + col);
            float2 v0, v1;
            v0.x = (float)acc[mi][ni][0] * sf0 * av.x + bv.x;
            v0.y = (float)acc[mi][ni][1] * sf0 * av.y + bv.y;
            v1.x = (float)acc[mi][ni][2] * sf1 * av.x + bv.x;
            v1.y = (float)acc[mi][ni][3] * sf1 * av.y + bv.y;
            *reinterpret_cast<float2*>(out + (size_t)r0 * OO + col) = v0;
            *reinterpret_cast<float2*>(out + (size_t)(r0 + 8) * OO + col) = v1;
        }
    }
#undef LOAD_STAGE
}

// ---------------- host ----------------
extern "C" void kernel_launch(void* const* d_in, const int* in_sizes, int n_in,
                              void* d_out, int out_size) {
    const float* x     = (const float*)d_in[0];
    const int*   nz    = (const int*)d_in[1];
    const int*   sgn   = (const int*)d_in[2];
    const float* bias  = (const float*)d_in[3];
    const float* alpha = (const float*)d_in[4];
    float* out = (float*)d_out;

    unpack_w_kernel<<<(OO * (KK / 32)) / 256, 256>>>(nz, sgn);
    quantize_x_kernel<<<MM, 256>>>((const float4*)x);

    cudaFuncSetAttribute(gemm_kernel, cudaFuncAttributeMaxDynamicSharedMemorySize, SMEM_BYTES);

    gemm_kernel<<<(MM / BM) * (OO / BN), 256, SMEM_BYTES>>>(alpha, bias, out);
}